// round 9
// baseline (speedup 1.0000x reference)
#include <cuda_runtime.h>
#include <cstdint>

// PhiCell: Phi is identity => outputs = inputs * k; new_state = outputs[T-1].
// R9: TMA bulk-copy data path. Per-CTA: cp.async.bulk (global->smem, mbarrier),
// scale in SMEM, cp.async.bulk (smem->global, bulk_group). Bypasses per-thread
// LDG/STG + L1tex wavefront queue, which 4 rounds of evidence say is where the
// ~2.1 TB/s ceiling lives (no chip pipe above 28% in any variant).

#define THREADS     256
#define TILE_BYTES  32768                 // 32 KB tile per CTA
#define TILE_FLOATS (TILE_BYTES / 4)      // 8192
#define TILE_VEC4   (TILE_BYTES / 16)     // 2048 float4
#define V4_PER_THR  (TILE_VEC4 / THREADS) // 8

__device__ __forceinline__ uint32_t smem_u32(const void* p) {
    uint32_t a;
    asm("{ .reg .u64 t; cvta.to.shared.u64 t, %1; cvt.u32.u64 %0, t; }"
        : "=r"(a) : "l"(p));
    return a;
}

__global__ void __launch_bounds__(THREADS, 1) phicell_tma(
    const float* __restrict__ in,
    const float* __restrict__ kptr,
    float*       __restrict__ out,
    int n, int out_size)
{
    __shared__ __align__(128) float tile[TILE_FLOATS];
    __shared__ __align__(8)  uint64_t mbar;

    const uint32_t smem_tile = smem_u32(tile);
    const uint32_t smem_bar  = smem_u32(&mbar);
    const int tid = threadIdx.x;

    const size_t goff = (size_t)blockIdx.x * TILE_FLOATS;
    const float* gsrc = in  + goff;
    float*       gdst = out + goff;

    if (tid == 0) {
        asm volatile("mbarrier.init.shared.b64 [%0], 1;" :: "r"(smem_bar) : "memory");
    }
    __syncthreads();

    if (tid == 0) {
        asm volatile("mbarrier.arrive.expect_tx.shared.b64 _, [%0], %1;"
                     :: "r"(smem_bar), "r"((uint32_t)TILE_BYTES) : "memory");
        asm volatile("cp.async.bulk.shared::cta.global.mbarrier::complete_tx::bytes "
                     "[%0], [%1], %2, [%3];"
                     :: "r"(smem_tile), "l"(gsrc), "r"((uint32_t)TILE_BYTES),
                        "r"(smem_bar) : "memory");
    }

    // Wait for TMA load (parity 0)
    {
        uint32_t done;
        asm volatile(
            "{\n\t.reg .pred p;\n\t"
            "mbarrier.try_wait.parity.acquire.cta.shared::cta.b64 p, [%1], 0;\n\t"
            "selp.b32 %0, 1, 0, p;\n\t}"
            : "=r"(done) : "r"(smem_bar) : "memory");
        if (!done) {
            asm volatile(
                "{\n\t.reg .pred P1;\n\t"
                "W_%=:\n\t"
                "mbarrier.try_wait.parity.acquire.cta.shared::cta.b64 P1, [%0], 0, 0x989680;\n\t"
                "@P1 bra.uni D_%=;\n\t"
                "bra.uni W_%=;\n\t"
                "D_%=:\n\t}"
                :: "r"(smem_bar) : "memory");
        }
    }

    // Scale in SMEM: conflict-free float4 strided access
    const float k = __ldg(kptr);
    float4* t4 = reinterpret_cast<float4*>(tile);
#pragma unroll
    for (int j = 0; j < V4_PER_THR; ++j) {
        float4 v = t4[tid + j * THREADS];
        v.x *= k; v.y *= k; v.z *= k; v.w *= k;
        t4[tid + j * THREADS] = v;
    }
    __syncthreads();

    // Order generic-proxy STS before async-proxy bulk read, then store tile
    if (tid == 0) {
        asm volatile("fence.proxy.async.shared::cta;" ::: "memory");
        asm volatile("cp.async.bulk.global.shared::cta.bulk_group [%0], [%1], %2;"
                     :: "l"(gdst), "r"(smem_tile), "r"((uint32_t)TILE_BYTES)
                     : "memory");
        asm volatile("cp.async.bulk.commit_group;" ::: "memory");
        asm volatile("cp.async.bulk.wait_group.read 0;" ::: "memory");
    }

    // Last block writes the state slot(s): out[n..out_size) = in[n-1]*k
    if (blockIdx.x == gridDim.x - 1 && tid == 0) {
        const float last = __ldg(&in[n - 1]) * k;
        for (int s = n; s < out_size; ++s) out[s] = last;
    }
}

// Generic fallback for shapes not divisible by the tile size.
__global__ void __launch_bounds__(256) phicell_generic(
    const float* __restrict__ in,
    const float* __restrict__ kptr,
    float*       __restrict__ out,
    int n, int out_size)
{
    const float k = __ldg(kptr);
    const int i = blockIdx.x * blockDim.x + threadIdx.x;
    const int base = i << 2;
    if (base + 3 < n) {
        float4 v = *reinterpret_cast<const float4*>(in + base);
        v.x *= k; v.y *= k; v.z *= k; v.w *= k;
        *reinterpret_cast<float4*>(out + base) = v;
        if (base + 4 == n)
            for (int j = n; j < out_size; ++j) out[j] = v.w;
    } else if (base < n) {
        float last = 0.f;
        for (int idx = base; idx < n; ++idx) { last = in[idx] * k; out[idx] = last; }
        for (int j = n; j < out_size; ++j) out[j] = last;
    }
}

extern "C" void kernel_launch(void* const* d_in, const int* in_sizes, int n_in,
                              void* d_out, int out_size)
{
    const float* in  = (const float*)d_in[0];   // inputs [1, T]
    // d_in[1] = state [1,1] (unused: Phi identity -> output state-independent)
    const float* kpt = (const float*)d_in[2];   // kernel [1,1]
    float* out = (float*)d_out;

    const int n = in_sizes[0];

    if ((n % TILE_FLOATS) == 0) {
        const int blk = n / TILE_FLOATS;        // 512 for T=4194304
        phicell_tma<<<blk, THREADS>>>(in, kpt, out, n, out_size);
    } else {
        const int nt  = (n + 3) >> 2;
        const int blk = (nt + 255) / 256;
        phicell_generic<<<blk > 0 ? blk : 1, 256>>>(in, kpt, out, n, out_size);
    }
}

// round 10
// speedup vs baseline: 1.4903x; 1.4903x over previous
#include <cuda_runtime.h>
#include <cstdint>

// PhiCell: Phi is identity => outputs = inputs * k; new_state = outputs[T-1].
// Converged streaming-scale kernel. Final micro-knob under test:
//   - ld.global.nc.L2::256B : 256B L2 prefetch granule per load request
//     (halves DRAM fetch requests for a sequential stream)
//   - st.global.cs          : evict-first stores, preserve L2 for the reads
// Shape: exact cover, 1024 blocks x 256 threads x 4 float4, phase-fenced.

#define VPT 4
#define THREADS 256

__device__ __forceinline__ float4 ldg_nc_256B(const float4* p) {
    float4 v;
    asm volatile("ld.global.nc.L2::256B.v4.f32 {%0,%1,%2,%3}, [%4];"
                 : "=f"(v.x), "=f"(v.y), "=f"(v.z), "=f"(v.w) : "l"(p));
    return v;
}
__device__ __forceinline__ void stg_cs(float4* p, float4 v) {
    asm volatile("st.global.cs.v4.f32 [%4], {%0,%1,%2,%3};"
                 :: "f"(v.x), "f"(v.y), "f"(v.z), "f"(v.w), "l"(p) : "memory");
}

__global__ void __launch_bounds__(THREADS, 1) phicell_final(
    const float4* __restrict__ in4,
    const float*  __restrict__ kptr,
    float4*       __restrict__ out4,
    int n, int out_size)
{
    const int base = blockIdx.x * (THREADS * VPT) + threadIdx.x;
    const float4* ip = in4 + base;
    float4*       op = out4 + base;

    // ---- load phase: 4 independent 256B-granule loads ----
    float4 v0 = ldg_nc_256B(ip + 0 * THREADS);
    float4 v1 = ldg_nc_256B(ip + 1 * THREADS);
    float4 v2 = ldg_nc_256B(ip + 2 * THREADS);
    float4 v3 = ldg_nc_256B(ip + 3 * THREADS);
    const float k = __ldg(kptr);

    asm volatile("" ::: "memory");   // keep loads front-batched

    v0.x *= k; v0.y *= k; v0.z *= k; v0.w *= k;
    v1.x *= k; v1.y *= k; v1.z *= k; v1.w *= k;
    v2.x *= k; v2.y *= k; v2.z *= k; v2.w *= k;
    v3.x *= k; v3.y *= k; v3.z *= k; v3.w *= k;

    stg_cs(op + 0 * THREADS, v0);
    stg_cs(op + 1 * THREADS, v1);
    stg_cs(op + 2 * THREADS, v2);
    stg_cs(op + 3 * THREADS, v3);

    // Owner of the final float4 writes the state slot(s).
    if (base + 3 * THREADS == (n >> 2) - 1) {
        float* outs = (float*)out4;
        for (int s = n; s < out_size; ++s) outs[s] = v3.w;
    }
}

// Generic fallback for shapes not divisible by the tile.
__global__ void __launch_bounds__(256) phicell_generic(
    const float* __restrict__ in,
    const float* __restrict__ kptr,
    float*       __restrict__ out,
    int n, int out_size)
{
    const float k = __ldg(kptr);
    const int i = blockIdx.x * blockDim.x + threadIdx.x;
    const int base = i << 2;
    if (base + 3 < n) {
        float4 v = *reinterpret_cast<const float4*>(in + base);
        v.x *= k; v.y *= k; v.z *= k; v.w *= k;
        *reinterpret_cast<float4*>(out + base) = v;
        if (base + 4 == n)
            for (int j = n; j < out_size; ++j) out[j] = v.w;
    } else if (base < n) {
        float last = 0.f;
        for (int idx = base; idx < n; ++idx) { last = in[idx] * k; out[idx] = last; }
        for (int j = n; j < out_size; ++j) out[j] = last;
    }
}

extern "C" void kernel_launch(void* const* d_in, const int* in_sizes, int n_in,
                              void* d_out, int out_size)
{
    const float* in  = (const float*)d_in[0];   // inputs [1, T]
    // d_in[1] = state [1,1] (unused: Phi identity -> output state-independent)
    const float* kpt = (const float*)d_in[2];   // kernel [1,1]
    float* out = (float*)d_out;

    const int n = in_sizes[0];
    const int per_block = THREADS * VPT * 4;    // 4096 elements per block

    if ((n % per_block) == 0) {
        const int blk = n / per_block;          // 1024 for T=4194304
        phicell_final<<<blk, THREADS>>>(
            (const float4*)in, kpt, (float4*)out, n, out_size);
    } else {
        const int nt  = (n + 3) >> 2;
        const int blk = (nt + 255) / 256;
        phicell_generic<<<blk > 0 ? blk : 1, 256>>>(in, kpt, out, n, out_size);
    }
}